// round 8
// baseline (speedup 1.0000x reference)
#include <cuda_runtime.h>
#include <cuda_bf16.h>
#include <cstdint>

#define BB 8
#define NN 8192
#define CIN 64
#define CO 128
#define SS 2048
#define KK 16

typedef unsigned long long ull;
typedef unsigned int u32;

// ---------------- scratch (static device globals; no allocation) ----------------
__device__ float g_y1[(size_t)BB * CO * NN];     // conv1 pre-BN   [B][C][N]
__device__ float g_y2[(size_t)BB * CO * NN];     // conv2 pre-BN   [B][C][N]
__device__ float g_f2[(size_t)BB * NN * CO];     // conv2 post-BN  [B][N][C] (transposed)
__device__ float g_a1[CO], g_b1s[CO], g_a2[CO], g_b2s[CO];
__device__ int   g_knn[(size_t)BB * SS * KK];

// ---------------- packed f32x2 helpers (per-lane RN, identical to scalar) --------
__device__ __forceinline__ ull f2add(ull a, ull b) {
    ull r; asm("add.rn.f32x2 %0,%1,%2;" : "=l"(r) : "l"(a), "l"(b)); return r;
}
__device__ __forceinline__ ull f2mul(ull a, ull b) {
    ull r; asm("mul.rn.f32x2 %0,%1,%2;" : "=l"(r) : "l"(a), "l"(b)); return r;
}
__device__ __forceinline__ ull pack2(float lo, float hi) {
    ull r; asm("mov.b64 %0,{%1,%2};" : "=l"(r) : "f"(lo), "f"(hi)); return r;
}
__device__ __forceinline__ float2 unpack2(ull v) {
    float2 r; asm("mov.b64 {%0,%1},%2;" : "=f"(r.x), "=f"(r.y) : "l"(v)); return r;
}

__device__ __forceinline__ u32 smem_u32(const void* p) {
    u32 a;
    asm("{ .reg .u64 t; cvta.to.shared.u64 t, %1; cvt.u32.u64 %0, t; }" : "=r"(a) : "l"(p));
    return a;
}

__device__ __forceinline__ void mbar_wait_cluster(u32 mbar, unsigned parity) {
    u32 done;
    do {
        asm volatile(
            "{\n\t.reg .pred p;\n\t"
            "mbarrier.try_wait.parity.acquire.cluster.shared::cta.b64 p, [%1], %2, 0x989680;\n\t"
            "selp.b32 %0, 1, 0, p;\n\t}"
            : "=r"(done) : "r"(mbar), "r"(parity) : "memory");
    } while (!done);
}

// =================================================================================
// FPS: 2-CTA cluster per batch (grid (2, BB)). Each CTA owns 4096 points
// (4/thread, packed f32x2). Per iteration: per-warp u64 (max,first-idx) key ->
// STS -> local bar -> warp0 reduces 32 keys, lane0 writes CTA key to both CTAs'
// ping-pong exchange slots via DSMEM and arrives on both mbarriers -> all wait
// (acquire.cluster) -> max of 2 keys = global argmax, identical in both CTAs.
// Distance formula matches reference bit-exactly: (dx*dx + dy*dy) + dz*dz, no FMA.
// =================================================================================
__global__ void __cluster_dims__(2, 1, 1) __launch_bounds__(1024, 1)
fps_kernel(const float* __restrict__ points, float* __restrict__ cent)
{
    __shared__ ull sWKey[32];
    __shared__ ull sExch[2][2];                 // [phase][rank]
    __shared__ __align__(8) ull sMbar;

    const int rank = blockIdx.x;                // 0/1 within cluster
    const int b = blockIdx.y;
    const int t = threadIdx.x;
    const int lane = t & 31, warp = t >> 5;
    const float* P = points + (size_t)b * 3 * NN;
    float* C = cent + (size_t)b * 3 * SS;

    const u32 mbar = smem_u32(&sMbar);
    u32 peerMbar, peerEx0;
    asm("mapa.shared::cluster.u32 %0, %1, %2;" : "=r"(peerMbar) : "r"(mbar), "r"(rank ^ 1));
    const u32 exBase = smem_u32(&sExch[0][0]);
    asm("mapa.shared::cluster.u32 %0, %1, %2;" : "=r"(peerEx0) : "r"(exBase), "r"(rank ^ 1));

    if (t == 0) {
        asm volatile("mbarrier.init.shared.b64 [%0], %1;" :: "r"(mbar), "r"(2u) : "memory");
    }
    // cluster-wide: mbarrier init visible before any remote arrive
    asm volatile("barrier.cluster.arrive.aligned;" ::: "memory");
    asm volatile("barrier.cluster.wait.aligned;" ::: "memory");

    const float x0 = __ldg(&P[0]);
    const float y0 = __ldg(&P[NN]);
    const float z0 = __ldg(&P[2 * NN]);
    const ull nx0 = pack2(-x0, -x0), ny0 = pack2(-y0, -y0), nz0 = pack2(-z0, -z0);

    // this CTA's pairs: global float2 index g = rank*2048 + t + 1024*q  (q < 2)
    const float2* Px = (const float2*)P;
    const float2* Py = (const float2*)(P + NN);
    const float2* Pz = (const float2*)(P + 2 * NN);
    const int gp0 = rank * 2048 + t;            // q=0 pair
    const int gp1 = gp0 + 1024;                 // q=1 pair
    const int gbase0 = 2 * gp0;                 // global point ids
    const int gbase1 = 2 * gp1;

    ull px[2], py[2], pz[2];
    float dd[4];
    {
        const float2 vx0 = Px[gp0], vy0 = Py[gp0], vz0 = Pz[gp0];
        const float2 vx1 = Px[gp1], vy1 = Py[gp1], vz1 = Pz[gp1];
        px[0] = pack2(vx0.x, vx0.y); py[0] = pack2(vy0.x, vy0.y); pz[0] = pack2(vz0.x, vz0.y);
        px[1] = pack2(vx1.x, vx1.y); py[1] = pack2(vy1.x, vy1.y); pz[1] = pack2(vz1.x, vz1.y);
#pragma unroll
        for (int q = 0; q < 2; q++) {
            const ull dx = f2add(px[q], nx0);
            const ull dy = f2add(py[q], ny0);
            const ull dz = f2add(pz[q], nz0);
            const ull s = f2add(f2add(f2mul(dx, dx), f2mul(dy, dy)), f2mul(dz, dz));
            const float2 sv = unpack2(s);
            dd[2 * q] = sv.x; dd[2 * q + 1] = sv.y;
        }
    }

    // per-warp u64 key: (max_bits << 32) | (8191 - first_index_at_max)
    {
        const float m = fmaxf(fmaxf(dd[0], dd[1]), fmaxf(dd[2], dd[3]));
        int mi = 0x7fffffff;
        if (dd[3] == m) mi = gbase1 + 1;
        if (dd[2] == m) mi = gbase1;
        if (dd[1] == m) mi = gbase0 + 1;
        if (dd[0] == m) mi = gbase0;
        ull key = ((ull)__float_as_uint(m) << 32) | (ull)(unsigned)(8191 - mi);
#pragma unroll
        for (int o = 16; o; o >>= 1) {
            const ull k2 = __shfl_xor_sync(0xffffffffu, key, o);
            key = (k2 > key) ? k2 : key;
        }
        if (lane == 0) sWKey[warp] = key;
    }

    if (rank == 0 && t == 0) { C[0] = x0; C[SS] = y0; C[2 * SS] = z0; }
    __syncthreads();

    unsigned ph = 0;
    for (int s = 1; s < SS; s++) {
        // warp0: reduce 32 warp keys -> CTA key, exchange with peer
        if (warp == 0) {
            ull k = sWKey[lane];
#pragma unroll
            for (int o = 16; o; o >>= 1) {
                const ull k2 = __shfl_xor_sync(0xffffffffu, k, o);
                k = (k2 > k) ? k2 : k;
            }
            if (lane == 0) {
                sExch[ph][rank] = k;                                  // local slot
                const u32 peerSlot = peerEx0 + (ph * 2 + rank) * 8;
                asm volatile("st.shared::cluster.u64 [%0], %1;" :: "r"(peerSlot), "l"(k) : "memory");
                asm volatile("mbarrier.arrive.release.cluster.shared::cta.b64 _, [%0];"
                             :: "r"(mbar) : "memory");
                asm volatile("mbarrier.arrive.release.cluster.shared::cluster.b64 _, [%0];"
                             :: "r"(peerMbar) : "memory");
            }
        }
        mbar_wait_cluster(mbar, ph);

        const ull k0 = sExch[ph][0], k1 = sExch[ph][1];
        const ull kg = (k1 > k0) ? k1 : k0;
        const int widx = 8191 - (int)(unsigned)(kg & 0xffffffffu);

        const float cx = __ldg(&P[widx]);
        const float cy = __ldg(&P[NN + widx]);
        const float cz = __ldg(&P[2 * NN + widx]);
        if (rank == 0 && t == 0) { C[s] = cx; C[SS + s] = cy; C[2 * SS + s] = cz; }

        // update running min-distances (packed, bit-exact)
        const ull ncx = pack2(-cx, -cx), ncy = pack2(-cy, -cy), ncz = pack2(-cz, -cz);
#pragma unroll
        for (int q = 0; q < 2; q++) {
            const ull dx = f2add(px[q], ncx);
            const ull dy = f2add(py[q], ncy);
            const ull dz = f2add(pz[q], ncz);
            const ull d2 = f2add(f2add(f2mul(dx, dx), f2mul(dy, dy)), f2mul(dz, dz));
            const float2 dv = unpack2(d2);
            dd[2 * q]     = fminf(dd[2 * q], dv.x);
            dd[2 * q + 1] = fminf(dd[2 * q + 1], dv.y);
        }

        // per-warp key for next iteration
        const float m = fmaxf(fmaxf(dd[0], dd[1]), fmaxf(dd[2], dd[3]));
        int mi = 0x7fffffff;
        if (dd[3] == m) mi = gbase1 + 1;
        if (dd[2] == m) mi = gbase1;
        if (dd[1] == m) mi = gbase0 + 1;
        if (dd[0] == m) mi = gbase0;
        ull key = ((ull)__float_as_uint(m) << 32) | (ull)(unsigned)(8191 - mi);
#pragma unroll
        for (int o = 16; o; o >>= 1) {
            const ull k2 = __shfl_xor_sync(0xffffffffu, key, o);
            key = (k2 > key) ? k2 : key;
        }
        if (lane == 0) sWKey[warp] = key;

        __syncthreads();          // sWKey ready for warp0; sExch reads done
        ph ^= 1;
    }
}

// =================================================================================
// GEMM1: y1[b][o][n] = W1[o][:] . feats[b][:][n] + b1[o]      (128x64 @ 64xN)
// =================================================================================
__global__ __launch_bounds__(256) void gemm1_kernel(const float* __restrict__ feats,
                                                    const float* __restrict__ W1,
                                                    const float* __restrict__ b1)
{
    __shared__ float As[CIN][CO];   // As[k][o]  (W transposed)
    __shared__ float Xs[CIN][64];
    const int b = blockIdx.y;
    const int n0 = blockIdx.x * 64;
    const int tid = threadIdx.x;
    const int tx = tid & 15, ty = tid >> 4;

    const float4* W4 = (const float4*)W1;                  // [128][16] float4
#pragma unroll
    for (int q = 0; q < 8; q++) {
        const int f = tid + 256 * q;                       // 0..2047
        const int o = f & 127;
        const int kq = f >> 7;                             // 0..15
        const float4 w = W4[o * 16 + kq];
        As[kq * 4 + 0][o] = w.x; As[kq * 4 + 1][o] = w.y;
        As[kq * 4 + 2][o] = w.z; As[kq * 4 + 3][o] = w.w;
    }
    const float* X = feats + (size_t)b * CIN * NN + n0;
#pragma unroll
    for (int r = 0; r < 16; r++) {
        const int e = tid + 256 * r;                       // 0..4095
        const int c = e >> 6, j = e & 63;
        Xs[c][j] = X[(size_t)c * NN + j];
    }
    __syncthreads();

    float acc[8][4];
#pragma unroll
    for (int i = 0; i < 8; i++)
#pragma unroll
        for (int j = 0; j < 4; j++) acc[i][j] = 0.f;

    const int ro = ty * 4, co = tx * 4;
#pragma unroll 4
    for (int k = 0; k < CIN; k++) {
        float a[8], bv[4];
        *(float4*)&a[0] = *(const float4*)&As[k][ro];
        *(float4*)&a[4] = *(const float4*)&As[k][ro + 64];
        *(float4*)&bv[0] = *(const float4*)&Xs[k][co];
#pragma unroll
        for (int i = 0; i < 8; i++)
#pragma unroll
            for (int j = 0; j < 4; j++) acc[i][j] = fmaf(a[i], bv[j], acc[i][j]);
    }

    float* Y = g_y1 + (size_t)b * CO * NN + n0;
#pragma unroll
    for (int i = 0; i < 8; i++) {
        const int o = (i < 4) ? (ro + i) : (64 + ro + i - 4);
        const float bias = __ldg(&b1[o]);
        float4 v = make_float4(acc[i][0] + bias, acc[i][1] + bias,
                               acc[i][2] + bias, acc[i][3] + bias);
        *(float4*)&Y[(size_t)o * NN + co] = v;
    }
}

// =================================================================================
// BN stats per channel  ->  affine (a, b):  y_bn = max(a*y + b, 0)
// =================================================================================
__device__ __forceinline__ void stats_impl(const float* __restrict__ y,
                                           const float* __restrict__ gamma,
                                           const float* __restrict__ beta,
                                           float* __restrict__ a,
                                           float* __restrict__ bs)
{
    const int c = blockIdx.x, t = threadIdx.x;
    float s = 0.f, q = 0.f;
    const float* base = y + (size_t)c * NN;
    for (int b = 0; b < BB; b++) {
        const float* p = base + (size_t)b * CO * NN;
        for (int i = t; i < NN; i += 256) { const float v = p[i]; s += v; q = fmaf(v, v, q); }
    }
    __shared__ float ssm[256], qsm[256];
    ssm[t] = s; qsm[t] = q; __syncthreads();
    for (int o = 128; o; o >>= 1) {
        if (t < o) { ssm[t] += ssm[t + o]; qsm[t] += qsm[t + o]; }
        __syncthreads();
    }
    if (t == 0) {
        const float mean = ssm[0] * (1.f / 65536.f);
        const float var = qsm[0] * (1.f / 65536.f) - mean * mean;
        const float inv = rsqrtf(fmaxf(var, 0.f) + 1e-5f);
        const float av = gamma[c] * inv;
        a[c] = av;
        bs[c] = beta[c] - mean * av;
    }
}
__global__ __launch_bounds__(256) void stats1_kernel(const float* __restrict__ g,
                                                     const float* __restrict__ be)
{ stats_impl(g_y1, g, be, g_a1, g_b1s); }
__global__ __launch_bounds__(256) void stats2_kernel(const float* __restrict__ g,
                                                     const float* __restrict__ be)
{ stats_impl(g_y2, g, be, g_a2, g_b2s); }

// =================================================================================
// GEMM2 with fused BN1+ReLU applied to the input tile   (128x128 @ 128xN)
// =================================================================================
__global__ __launch_bounds__(256) void gemm2_kernel(const float* __restrict__ W2,
                                                    const float* __restrict__ b2)
{
    __shared__ float As[64][CO];
    __shared__ float Xs[64][64];
    const int b = blockIdx.y, n0 = blockIdx.x * 64;
    const int tid = threadIdx.x, tx = tid & 15, ty = tid >> 4;

    float acc[8][4];
#pragma unroll
    for (int i = 0; i < 8; i++)
#pragma unroll
        for (int j = 0; j < 4; j++) acc[i][j] = 0.f;

    const float4* W4 = (const float4*)W2;                  // [128][32] float4
    const float* Ybase = g_y1 + (size_t)b * CO * NN + n0;
    const int ro = ty * 4, co = tx * 4;

    for (int kt = 0; kt < 2; kt++) {
        if (kt) __syncthreads();
#pragma unroll
        for (int q = 0; q < 8; q++) {
            const int f = tid + 256 * q;
            const int o = f & 127;
            const int kq = f >> 7;
            const float4 w = W4[o * 32 + kt * 16 + kq];
            As[kq * 4 + 0][o] = w.x; As[kq * 4 + 1][o] = w.y;
            As[kq * 4 + 2][o] = w.z; As[kq * 4 + 3][o] = w.w;
        }
#pragma unroll
        for (int r = 0; r < 16; r++) {
            const int e = tid + 256 * r;
            const int cl = e >> 6, j = e & 63;
            const int c = kt * 64 + cl;
            const float v = Ybase[(size_t)c * NN + j];
            Xs[cl][j] = fmaxf(fmaf(g_a1[c], v, g_b1s[c]), 0.f);
        }
        __syncthreads();
#pragma unroll 4
        for (int k = 0; k < 64; k++) {
            float a[8], bv[4];
            *(float4*)&a[0] = *(const float4*)&As[k][ro];
            *(float4*)&a[4] = *(const float4*)&As[k][ro + 64];
            *(float4*)&bv[0] = *(const float4*)&Xs[k][co];
#pragma unroll
            for (int i = 0; i < 8; i++)
#pragma unroll
                for (int j = 0; j < 4; j++) acc[i][j] = fmaf(a[i], bv[j], acc[i][j]);
        }
    }

    float* Y = g_y2 + (size_t)b * CO * NN + n0;
#pragma unroll
    for (int i = 0; i < 8; i++) {
        const int o = (i < 4) ? (ro + i) : (64 + ro + i - 4);
        const float bias = __ldg(&b2[o]);
        float4 v = make_float4(acc[i][0] + bias, acc[i][1] + bias,
                               acc[i][2] + bias, acc[i][3] + bias);
        *(float4*)&Y[(size_t)o * NN + co] = v;
    }
}

// =================================================================================
// BN2 + ReLU + transpose:  g_f2[b][n][c] = relu(a2[c]*y2[b][c][n] + b2s[c])
// =================================================================================
__global__ __launch_bounds__(256) void bn2t_kernel()
{
    __shared__ float tile[32][33];
    const int b = blockIdx.z, c0 = blockIdx.y * 32, n0 = blockIdx.x * 32;
    const int tx = threadIdx.x, ty = threadIdx.y;          // (32, 8)
#pragma unroll
    for (int i = 0; i < 4; i++) {
        const int c = c0 + ty + i * 8;
        const float v = g_y2[((size_t)b * CO + c) * NN + n0 + tx];
        tile[ty + i * 8][tx] = fmaxf(fmaf(g_a2[c], v, g_b2s[c]), 0.f);
    }
    __syncthreads();
#pragma unroll
    for (int i = 0; i < 4; i++) {
        const int n = n0 + ty + i * 8;
        g_f2[((size_t)b * NN + n) * CO + c0 + tx] = tile[tx][ty + i * 8];
    }
}

// =================================================================================
// kNN: one thread per centroid, streaming top-16 over smem point tiles.
// =================================================================================
__global__ __launch_bounds__(128) void knn_kernel(const float* __restrict__ points,
                                                  const float* __restrict__ cent)
{
    __shared__ float sx[2048], sy[2048], sz[2048], sp2[2048];
    const int b = blockIdx.y;
    const int s = blockIdx.x * 128 + threadIdx.x;
    const float* P = points + (size_t)b * 3 * NN;
    const float* C = cent + (size_t)b * 3 * SS;

    const float cx = C[s], cy = C[SS + s], cz = C[2 * SS + s];
    const float c2 = __fadd_rn(__fadd_rn(__fmul_rn(cx, cx), __fmul_rn(cy, cy)),
                               __fmul_rn(cz, cz));

    float bd[KK]; int bi[KK];
#pragma unroll
    for (int j = 0; j < KK; j++) { bd[j] = 3.4e38f; bi[j] = 0x7fffffff; }
    float wd = 3.4e38f; int wi = 0x7fffffff; int ws = 0;

    for (int t0 = 0; t0 < NN; t0 += 2048) {
        __syncthreads();
        for (int i = threadIdx.x; i < 2048; i += 128) {
            const float x = P[t0 + i], y = P[NN + t0 + i], z = P[2 * NN + t0 + i];
            sx[i] = x; sy[i] = y; sz[i] = z;
            sp2[i] = __fadd_rn(__fadd_rn(__fmul_rn(x, x), __fmul_rn(y, y)), __fmul_rn(z, z));
        }
        __syncthreads();
        for (int i = 0; i < 2048; i++) {
            const float dot = __fadd_rn(__fadd_rn(__fmul_rn(cx, sx[i]), __fmul_rn(cy, sy[i])),
                                        __fmul_rn(cz, sz[i]));
            const float d = __fsub_rn(__fadd_rn(c2, sp2[i]), __fmul_rn(2.0f, dot));
            if (d < wd) {
                bd[ws] = d; bi[ws] = t0 + i;
                wd = bd[0]; wi = bi[0]; ws = 0;
#pragma unroll
                for (int j = 1; j < KK; j++) {
                    if (bd[j] > wd || (bd[j] == wd && bi[j] > wi)) {
                        wd = bd[j]; wi = bi[j]; ws = j;
                    }
                }
            }
        }
    }

    int* kn = g_knn + ((size_t)b * SS + s) * KK;
#pragma unroll
    for (int j = 0; j < KK; j++) kn[j] = bi[j];
}

// =================================================================================
// Gather + mean over K neighbors:  out[b][c][s] = mean_k f2[b][knn[b][s][k]][c]
// =================================================================================
__global__ __launch_bounds__(128) void gather_kernel(float* __restrict__ out)
{
    const int b = blockIdx.y;
    const int s = blockIdx.x;
    const int c = threadIdx.x;                             // 128 channels
    const int* kn = g_knn + ((size_t)b * SS + s) * KK;
    float acc = 0.f;
#pragma unroll
    for (int j = 0; j < KK; j++) {
        const int n = __ldg(&kn[j]);
        acc += g_f2[((size_t)b * NN + n) * CO + c];
    }
    out[((size_t)b * CO + c) * SS + s] = acc * (1.0f / KK);
}

// =================================================================================
extern "C" void kernel_launch(void* const* d_in, const int* in_sizes, int n_in,
                              void* d_out, int out_size)
{
    const float* feats  = (const float*)d_in[0];
    const float* points = (const float*)d_in[1];
    const float* W1     = (const float*)d_in[2];
    const float* b1     = (const float*)d_in[3];
    const float* gamma1 = (const float*)d_in[4];
    const float* beta1  = (const float*)d_in[5];
    const float* W2     = (const float*)d_in[6];
    const float* b2     = (const float*)d_in[7];
    const float* gamma2 = (const float*)d_in[8];
    const float* beta2  = (const float*)d_in[9];

    float* out  = (float*)d_out;
    float* cent = out + (size_t)BB * CO * SS;              // centroids tail: [B][3][S]

    fps_kernel<<<dim3(2, BB), 1024>>>(points, cent);       // 2-CTA cluster per batch
    gemm1_kernel<<<dim3(NN / 64, BB), 256>>>(feats, W1, b1);
    stats1_kernel<<<CO, 256>>>(gamma1, beta1);
    gemm2_kernel<<<dim3(NN / 64, BB), 256>>>(W2, b2);
    stats2_kernel<<<CO, 256>>>(gamma2, beta2);
    bn2t_kernel<<<dim3(NN / 32, CO / 32, BB), dim3(32, 8)>>>();
    knn_kernel<<<dim3(SS / 128, BB), 128>>>(points, cent);
    gather_kernel<<<dim3(SS, BB), 128>>>(out);
}

// round 9
// speedup vs baseline: 1.8739x; 1.8739x over previous
#include <cuda_runtime.h>
#include <cuda_bf16.h>
#include <cstdint>

#define BB 8
#define NN 8192
#define CIN 64
#define CO 128
#define SS 2048
#define KK 16

typedef unsigned long long ull;

// ---------------- scratch (static device globals; no allocation) ----------------
__device__ float g_y1[(size_t)BB * CO * NN];     // conv1 pre-BN   [B][C][N]
__device__ float g_y2[(size_t)BB * CO * NN];     // conv2 pre-BN   [B][C][N]
__device__ float g_f2[(size_t)BB * NN * CO];     // conv2 post-BN  [B][N][C] (transposed)
__device__ float g_a1[CO], g_b1s[CO], g_a2[CO], g_b2s[CO];
__device__ float g_ps[2][CO][BB], g_pq[2][CO][BB];   // stats partials
__device__ int   g_knn[(size_t)BB * SS * KK];

// ---------------- packed f32x2 helpers (per-lane RN, identical to scalar) --------
__device__ __forceinline__ ull f2add(ull a, ull b) {
    ull r; asm("add.rn.f32x2 %0,%1,%2;" : "=l"(r) : "l"(a), "l"(b)); return r;
}
__device__ __forceinline__ ull f2mul(ull a, ull b) {
    ull r; asm("mul.rn.f32x2 %0,%1,%2;" : "=l"(r) : "l"(a), "l"(b)); return r;
}
__device__ __forceinline__ ull pack2(float lo, float hi) {
    ull r; asm("mov.b64 %0,{%1,%2};" : "=l"(r) : "f"(lo), "f"(hi)); return r;
}
__device__ __forceinline__ float2 unpack2(ull v) {
    float2 r; asm("mov.b64 {%0,%1},%2;" : "=f"(r.x), "=f"(r.y) : "l"(v)); return r;
}

// =================================================================================
// FPS (R3 structure + REDUX warp max): one CTA per batch, 8 points/thread packed,
// 2 barriers/iter, ping-pong atomicMax(float-bits) + atomicMin(index) slots.
// Warp max = fmaxf tree (3 levels) + single REDUX.MAX.U32 (dd >= 0 -> order ok).
// Distance formula matches reference bit-exactly: (dx*dx + dy*dy) + dz*dz, no FMA.
// =================================================================================
__global__ __launch_bounds__(1024, 1) void fps_kernel(const float* __restrict__ points,
                                                      float* __restrict__ cent)
{
    __shared__ int sMaxI[2];   // float-bits of global max
    __shared__ int sIdx[2];    // argmax index (first-index tiebreak)

    const int b = blockIdx.x;
    const int t = threadIdx.x;
    const int lane = t & 31;
    const float* P = points + (size_t)b * 3 * NN;
    float* C = cent + (size_t)b * 3 * SS;

    if (t == 0) { sMaxI[0] = 0; sMaxI[1] = 0; sIdx[0] = 0x7fffffff; sIdx[1] = 0x7fffffff; }

    const float x0 = __ldg(&P[0]);
    const float y0 = __ldg(&P[NN]);
    const float z0 = __ldg(&P[2 * NN]);
    const ull nx0 = pack2(-x0, -x0), ny0 = pack2(-y0, -y0), nz0 = pack2(-z0, -z0);

    const float2* Px = (const float2*)P;
    const float2* Py = (const float2*)(P + NN);
    const float2* Pz = (const float2*)(P + 2 * NN);

    ull px[4], py[4], pz[4];
    float dd[8];
#pragma unroll
    for (int q = 0; q < 4; q++) {
        const int i = t + 1024 * q;
        const float2 vx = Px[i], vy = Py[i], vz = Pz[i];
        px[q] = pack2(vx.x, vx.y); py[q] = pack2(vy.x, vy.y); pz[q] = pack2(vz.x, vz.y);
        const ull dx = f2add(px[q], nx0);
        const ull dy = f2add(py[q], ny0);
        const ull dz = f2add(pz[q], nz0);
        const ull s = f2add(f2add(f2mul(dx, dx), f2mul(dy, dy)), f2mul(dz, dz));
        const float2 sv = unpack2(s);
        dd[2 * q] = sv.x; dd[2 * q + 1] = sv.y;
    }
    // warp max: per-thread fmax tree + one REDUX
    float wm;
    {
        const float m = fmaxf(fmaxf(fmaxf(dd[0], dd[1]), fmaxf(dd[2], dd[3])),
                              fmaxf(fmaxf(dd[4], dd[5]), fmaxf(dd[6], dd[7])));
        wm = __uint_as_float(__reduce_max_sync(0xffffffffu, __float_as_uint(m)));
    }

    if (t == 0) { C[0] = x0; C[SS] = y0; C[2 * SS] = z0; }
    __syncthreads();   // slot init visible; first wm ready

    for (int s = 1; s < SS; s++) {
        const int c = s & 1;
        if (lane == 0) atomicMax(&sMaxI[c], __float_as_int(wm));
        __syncthreads();                                   // bar1
        const float gm = __int_as_float(sMaxI[c]);
        if (t == 0) { sMaxI[c ^ 1] = 0; sIdx[c ^ 1] = 0x7fffffff; }  // reset other slot
        if (wm == gm) {                                    // warp-uniform branch
            int mi = 0x7fffffff;
#pragma unroll
            for (int q = 0; q < 4; q++) {
                const int base = 2 * (t + 1024 * q);
                if (dd[2 * q] == gm)     mi = min(mi, base);
                if (dd[2 * q + 1] == gm) mi = min(mi, base + 1);
            }
            if (mi != 0x7fffffff) atomicMin(&sIdx[c], mi); // first-index tiebreak
        }
        __syncthreads();                                   // bar2
        const int widx = sIdx[c];
        const float cx = __ldg(&P[widx]);
        const float cy = __ldg(&P[NN + widx]);
        const float cz = __ldg(&P[2 * NN + widx]);
        if (t == 0) { C[s] = cx; C[SS + s] = cy; C[2 * SS + s] = cz; }

        const ull ncx = pack2(-cx, -cx), ncy = pack2(-cy, -cy), ncz = pack2(-cz, -cz);
#pragma unroll
        for (int q = 0; q < 4; q++) {
            const ull dx = f2add(px[q], ncx);
            const ull dy = f2add(py[q], ncy);
            const ull dz = f2add(pz[q], ncz);
            const ull d2 = f2add(f2add(f2mul(dx, dx), f2mul(dy, dy)), f2mul(dz, dz));
            const float2 dv = unpack2(d2);
            dd[2 * q]     = fminf(dd[2 * q], dv.x);
            dd[2 * q + 1] = fminf(dd[2 * q + 1], dv.y);
        }
        const float m = fmaxf(fmaxf(fmaxf(dd[0], dd[1]), fmaxf(dd[2], dd[3])),
                              fmaxf(fmaxf(dd[4], dd[5]), fmaxf(dd[6], dd[7])));
        wm = __uint_as_float(__reduce_max_sync(0xffffffffu, __float_as_uint(m)));
    }
}

// =================================================================================
// GEMM1: y1[b][o][n] = W1[o][:] . feats[b][:][n] + b1[o]      (128x64 @ 64xN)
// =================================================================================
__global__ __launch_bounds__(256) void gemm1_kernel(const float* __restrict__ feats,
                                                    const float* __restrict__ W1,
                                                    const float* __restrict__ b1)
{
    __shared__ float As[CIN][CO];   // As[k][o]  (W transposed)
    __shared__ float Xs[CIN][64];
    const int b = blockIdx.y;
    const int n0 = blockIdx.x * 64;
    const int tid = threadIdx.x;
    const int tx = tid & 15, ty = tid >> 4;

    const float4* W4 = (const float4*)W1;                  // [128][16] float4
#pragma unroll
    for (int q = 0; q < 8; q++) {
        const int f = tid + 256 * q;                       // 0..2047
        const int o = f & 127;
        const int kq = f >> 7;                             // 0..15
        const float4 w = W4[o * 16 + kq];
        As[kq * 4 + 0][o] = w.x; As[kq * 4 + 1][o] = w.y;
        As[kq * 4 + 2][o] = w.z; As[kq * 4 + 3][o] = w.w;
    }
    const float* X = feats + (size_t)b * CIN * NN + n0;
#pragma unroll
    for (int r = 0; r < 16; r++) {
        const int e = tid + 256 * r;                       // 0..4095
        const int c = e >> 6, j = e & 63;
        Xs[c][j] = X[(size_t)c * NN + j];
    }
    __syncthreads();

    float acc[8][4];
#pragma unroll
    for (int i = 0; i < 8; i++)
#pragma unroll
        for (int j = 0; j < 4; j++) acc[i][j] = 0.f;

    const int ro = ty * 4, co = tx * 4;
#pragma unroll 4
    for (int k = 0; k < CIN; k++) {
        float a[8], bv[4];
        *(float4*)&a[0] = *(const float4*)&As[k][ro];
        *(float4*)&a[4] = *(const float4*)&As[k][ro + 64];
        *(float4*)&bv[0] = *(const float4*)&Xs[k][co];
#pragma unroll
        for (int i = 0; i < 8; i++)
#pragma unroll
            for (int j = 0; j < 4; j++) acc[i][j] = fmaf(a[i], bv[j], acc[i][j]);
    }

    float* Y = g_y1 + (size_t)b * CO * NN + n0;
#pragma unroll
    for (int i = 0; i < 8; i++) {
        const int o = (i < 4) ? (ro + i) : (64 + ro + i - 4);
        const float bias = __ldg(&b1[o]);
        float4 v = make_float4(acc[i][0] + bias, acc[i][1] + bias,
                               acc[i][2] + bias, acc[i][3] + bias);
        *(float4*)&Y[(size_t)o * NN + co] = v;
    }
}

// =================================================================================
// BN stats, two-stage. Stage A: grid (CO, BB) partial sums. Stage B: finalize.
// =================================================================================
__global__ __launch_bounds__(256) void stats_part_kernel(int which)
{
    const float* y = which ? g_y2 : g_y1;
    const int c = blockIdx.x, b = blockIdx.y, t = threadIdx.x;
    const int lane = t & 31, warp = t >> 5;
    const float* p = y + ((size_t)b * CO + c) * NN;
    float s = 0.f, q = 0.f;
    for (int i = t; i < NN; i += 256) { const float v = p[i]; s += v; q = fmaf(v, v, q); }
#pragma unroll
    for (int o = 16; o; o >>= 1) {
        s += __shfl_xor_sync(0xffffffffu, s, o);
        q += __shfl_xor_sync(0xffffffffu, q, o);
    }
    __shared__ float ss[8], qs[8];
    if (lane == 0) { ss[warp] = s; qs[warp] = q; }
    __syncthreads();
    if (t == 0) {
        float S = 0.f, Q = 0.f;
#pragma unroll
        for (int w = 0; w < 8; w++) { S += ss[w]; Q += qs[w]; }
        g_ps[which][c][b] = S; g_pq[which][c][b] = Q;
    }
}

__global__ __launch_bounds__(CO) void stats_fin_kernel(const float* __restrict__ gamma,
                                                       const float* __restrict__ beta,
                                                       int which)
{
    const int c = threadIdx.x;
    float S = 0.f, Q = 0.f;
#pragma unroll
    for (int b = 0; b < BB; b++) { S += g_ps[which][c][b]; Q += g_pq[which][c][b]; }
    const float mean = S * (1.f / 65536.f);
    const float var = Q * (1.f / 65536.f) - mean * mean;
    const float inv = rsqrtf(fmaxf(var, 0.f) + 1e-5f);
    const float av = gamma[c] * inv;
    if (which) { g_a2[c] = av; g_b2s[c] = beta[c] - mean * av; }
    else       { g_a1[c] = av; g_b1s[c] = beta[c] - mean * av; }
}

// =================================================================================
// GEMM2 with fused BN1+ReLU applied to the input tile   (128x128 @ 128xN)
// =================================================================================
__global__ __launch_bounds__(256) void gemm2_kernel(const float* __restrict__ W2,
                                                    const float* __restrict__ b2)
{
    __shared__ float As[64][CO];
    __shared__ float Xs[64][64];
    const int b = blockIdx.y, n0 = blockIdx.x * 64;
    const int tid = threadIdx.x, tx = tid & 15, ty = tid >> 4;

    float acc[8][4];
#pragma unroll
    for (int i = 0; i < 8; i++)
#pragma unroll
        for (int j = 0; j < 4; j++) acc[i][j] = 0.f;

    const float4* W4 = (const float4*)W2;                  // [128][32] float4
    const float* Ybase = g_y1 + (size_t)b * CO * NN + n0;
    const int ro = ty * 4, co = tx * 4;

    for (int kt = 0; kt < 2; kt++) {
        if (kt) __syncthreads();
#pragma unroll
        for (int q = 0; q < 8; q++) {
            const int f = tid + 256 * q;
            const int o = f & 127;
            const int kq = f >> 7;
            const float4 w = W4[o * 32 + kt * 16 + kq];
            As[kq * 4 + 0][o] = w.x; As[kq * 4 + 1][o] = w.y;
            As[kq * 4 + 2][o] = w.z; As[kq * 4 + 3][o] = w.w;
        }
#pragma unroll
        for (int r = 0; r < 16; r++) {
            const int e = tid + 256 * r;
            const int cl = e >> 6, j = e & 63;
            const int c = kt * 64 + cl;
            const float v = Ybase[(size_t)c * NN + j];
            Xs[cl][j] = fmaxf(fmaf(g_a1[c], v, g_b1s[c]), 0.f);
        }
        __syncthreads();
#pragma unroll 4
        for (int k = 0; k < 64; k++) {
            float a[8], bv[4];
            *(float4*)&a[0] = *(const float4*)&As[k][ro];
            *(float4*)&a[4] = *(const float4*)&As[k][ro + 64];
            *(float4*)&bv[0] = *(const float4*)&Xs[k][co];
#pragma unroll
            for (int i = 0; i < 8; i++)
#pragma unroll
                for (int j = 0; j < 4; j++) acc[i][j] = fmaf(a[i], bv[j], acc[i][j]);
        }
    }

    float* Y = g_y2 + (size_t)b * CO * NN + n0;
#pragma unroll
    for (int i = 0; i < 8; i++) {
        const int o = (i < 4) ? (ro + i) : (64 + ro + i - 4);
        const float bias = __ldg(&b2[o]);
        float4 v = make_float4(acc[i][0] + bias, acc[i][1] + bias,
                               acc[i][2] + bias, acc[i][3] + bias);
        *(float4*)&Y[(size_t)o * NN + co] = v;
    }
}

// =================================================================================
// BN2 + ReLU + transpose:  g_f2[b][n][c] = relu(a2[c]*y2[b][c][n] + b2s[c])
// =================================================================================
__global__ __launch_bounds__(256) void bn2t_kernel()
{
    __shared__ float tile[32][33];
    const int b = blockIdx.z, c0 = blockIdx.y * 32, n0 = blockIdx.x * 32;
    const int tx = threadIdx.x, ty = threadIdx.y;          // (32, 8)
#pragma unroll
    for (int i = 0; i < 4; i++) {
        const int c = c0 + ty + i * 8;
        const float v = g_y2[((size_t)b * CO + c) * NN + n0 + tx];
        tile[ty + i * 8][tx] = fmaxf(fmaf(g_a2[c], v, g_b2s[c]), 0.f);
    }
    __syncthreads();
#pragma unroll
    for (int i = 0; i < 4; i++) {
        const int n = n0 + ty + i * 8;
        g_f2[((size_t)b * NN + n) * CO + c0 + tx] = tile[tx][ty + i * 8];
    }
}

// =================================================================================
// kNN: one thread per centroid, streaming top-16 over smem point tiles.
// =================================================================================
__global__ __launch_bounds__(128) void knn_kernel(const float* __restrict__ points,
                                                  const float* __restrict__ cent)
{
    __shared__ float sx[2048], sy[2048], sz[2048], sp2[2048];
    const int b = blockIdx.y;
    const int s = blockIdx.x * 128 + threadIdx.x;
    const float* P = points + (size_t)b * 3 * NN;
    const float* C = cent + (size_t)b * 3 * SS;

    const float cx = C[s], cy = C[SS + s], cz = C[2 * SS + s];
    const float c2 = __fadd_rn(__fadd_rn(__fmul_rn(cx, cx), __fmul_rn(cy, cy)),
                               __fmul_rn(cz, cz));

    float bd[KK]; int bi[KK];
#pragma unroll
    for (int j = 0; j < KK; j++) { bd[j] = 3.4e38f; bi[j] = 0x7fffffff; }
    float wd = 3.4e38f; int wi = 0x7fffffff; int ws = 0;

    for (int t0 = 0; t0 < NN; t0 += 2048) {
        __syncthreads();
        for (int i = threadIdx.x; i < 2048; i += 128) {
            const float x = P[t0 + i], y = P[NN + t0 + i], z = P[2 * NN + t0 + i];
            sx[i] = x; sy[i] = y; sz[i] = z;
            sp2[i] = __fadd_rn(__fadd_rn(__fmul_rn(x, x), __fmul_rn(y, y)), __fmul_rn(z, z));
        }
        __syncthreads();
        for (int i = 0; i < 2048; i++) {
            const float dot = __fadd_rn(__fadd_rn(__fmul_rn(cx, sx[i]), __fmul_rn(cy, sy[i])),
                                        __fmul_rn(cz, sz[i]));
            const float d = __fsub_rn(__fadd_rn(c2, sp2[i]), __fmul_rn(2.0f, dot));
            if (d < wd) {
                bd[ws] = d; bi[ws] = t0 + i;
                wd = bd[0]; wi = bi[0]; ws = 0;
#pragma unroll
                for (int j = 1; j < KK; j++) {
                    if (bd[j] > wd || (bd[j] == wd && bi[j] > wi)) {
                        wd = bd[j]; wi = bi[j]; ws = j;
                    }
                }
            }
        }
    }

    int* kn = g_knn + ((size_t)b * SS + s) * KK;
#pragma unroll
    for (int j = 0; j < KK; j++) kn[j] = bi[j];
}

// =================================================================================
// Gather + mean over K neighbors:  out[b][c][s] = mean_k f2[b][knn[b][s][k]][c]
// =================================================================================
__global__ __launch_bounds__(128) void gather_kernel(float* __restrict__ out)
{
    const int b = blockIdx.y;
    const int s = blockIdx.x;
    const int c = threadIdx.x;                             // 128 channels
    const int* kn = g_knn + ((size_t)b * SS + s) * KK;
    float acc = 0.f;
#pragma unroll
    for (int j = 0; j < KK; j++) {
        const int n = __ldg(&kn[j]);
        acc += g_f2[((size_t)b * NN + n) * CO + c];
    }
    out[((size_t)b * CO + c) * SS + s] = acc * (1.0f / KK);
}

// =================================================================================
extern "C" void kernel_launch(void* const* d_in, const int* in_sizes, int n_in,
                              void* d_out, int out_size)
{
    const float* feats  = (const float*)d_in[0];
    const float* points = (const float*)d_in[1];
    const float* W1     = (const float*)d_in[2];
    const float* b1     = (const float*)d_in[3];
    const float* gamma1 = (const float*)d_in[4];
    const float* beta1  = (const float*)d_in[5];
    const float* W2     = (const float*)d_in[6];
    const float* b2     = (const float*)d_in[7];
    const float* gamma2 = (const float*)d_in[8];
    const float* beta2  = (const float*)d_in[9];

    float* out  = (float*)d_out;
    float* cent = out + (size_t)BB * CO * SS;              // centroids tail: [B][3][S]

    fps_kernel<<<BB, 1024>>>(points, cent);
    gemm1_kernel<<<dim3(NN / 64, BB), 256>>>(feats, W1, b1);
    stats_part_kernel<<<dim3(CO, BB), 256>>>(0);
    stats_fin_kernel<<<1, CO>>>(gamma1, beta1, 0);
    gemm2_kernel<<<dim3(NN / 64, BB), 256>>>(W2, b2);
    stats_part_kernel<<<dim3(CO, BB), 256>>>(1);
    stats_fin_kernel<<<1, CO>>>(gamma2, beta2, 1);
    bn2t_kernel<<<dim3(NN / 32, CO / 32, BB), dim3(32, 8)>>>();
    knn_kernel<<<dim3(SS / 128, BB), 128>>>(points, cent);
    gather_kernel<<<dim3(SS, BB), 128>>>(out);
}